// round 2
// baseline (speedup 1.0000x reference)
#include <cuda_runtime.h>
#include <cstdint>

#define HH 1024
#define WW 1024
#define EPSV 1e-6f
#define BGW  1e-4f

// Scratch: per-pixel accumulator (r,g,b,wsum). 16 MB static device array.
__device__ float4 g_accum[HH * WW];

// ---------------------------------------------------------------------------
// Kernel 1: project points and scatter-add (w*feat, w) with one vector atomic.
// points row layout: [x, y, z, f0, f1, f2]
// camera: Rt (3x4 row-major, 12 floats) then fx, fy, cx, cy
//
// NOTE: all arithmetic feeding floor() uses explicit _rn intrinsics to match
// JAX's separately-rounded fp32 ops exactly (no FMA contraction). A contracted
// fma flips floor bins for points within ~1 ulp of a pixel boundary, which is
// what caused the 2.6e-3 rel error in round 1.
// ---------------------------------------------------------------------------
__global__ void splat_kernel(const float* __restrict__ pts,
                             const float* __restrict__ cam,
                             int n) {
    int i = blockIdx.x * blockDim.x + threadIdx.x;
    if (i >= n) return;

    const float2* p = reinterpret_cast<const float2*>(pts + 6ll * i);
    float2 a = __ldg(p + 0);   // x, y
    float2 b = __ldg(p + 1);   // z, f0
    float2 c = __ldg(p + 2);   // f1, f2
    float x = a.x, y = a.y, z = b.x;
    float f0 = b.y, f1 = c.x, f2 = c.y;

    // camera broadcast loads (L1-cached, all threads same address)
    float r00 = __ldg(cam + 0),  r01 = __ldg(cam + 1),  r02 = __ldg(cam + 2),  t0 = __ldg(cam + 3);
    float r10 = __ldg(cam + 4),  r11 = __ldg(cam + 5),  r12 = __ldg(cam + 6),  t1 = __ldg(cam + 7);
    float r20 = __ldg(cam + 8),  r21 = __ldg(cam + 9),  r22 = __ldg(cam + 10), t2 = __ldg(cam + 11);
    float fx  = __ldg(cam + 12), fy  = __ldg(cam + 13), cx = __ldg(cam + 14),  cy = __ldg(cam + 15);

    // strict rn arithmetic, no contraction
    float px = __fadd_rn(__fadd_rn(__fadd_rn(__fmul_rn(r00, x), __fmul_rn(r01, y)),
                                   __fmul_rn(r02, z)), t0);
    float py = __fadd_rn(__fadd_rn(__fadd_rn(__fmul_rn(r10, x), __fmul_rn(r11, y)),
                                   __fmul_rn(r12, z)), t1);
    float pz = __fadd_rn(__fadd_rn(__fadd_rn(__fmul_rn(r20, x), __fmul_rn(r21, y)),
                                   __fmul_rn(r22, z)), t2);

    float inv_z = __fdiv_rn(1.0f, fmaxf(pz, EPSV));
    // JAX order: (fx * px) * inv_z + cx, each op rounded
    float u = __fadd_rn(__fmul_rn(__fmul_rn(fx, px), inv_z), cx);
    float v = __fadd_rn(__fmul_rn(__fmul_rn(fy, py), inv_z), cy);

    // floor(u) in [0, W) <=> u in [0, W)
    bool valid = (pz > EPSV) & (u >= 0.0f) & (u < (float)WW)
                            & (v >= 0.0f) & (v < (float)HH);
    if (!valid) return;

    int ui = (int)floorf(u);
    int vi = (int)floorf(v);
    int idx = vi * WW + ui;

    float w = inv_z;
    float4* dst = &g_accum[idx];
    asm volatile("red.global.add.v4.f32 [%0], {%1, %2, %3, %4};"
                 :: "l"(dst),
                    "f"(__fmul_rn(w, f0)),
                    "f"(__fmul_rn(w, f1)),
                    "f"(__fmul_rn(w, f2)),
                    "f"(w)
                 : "memory");
}

// ---------------------------------------------------------------------------
// Kernel 2: normalize. Each thread handles 4 pixels so env/out I/O is float4.
// out[pix] = (accum.rgb + BGW * env.rgb) / (accum.w + BGW)   -- true division,
// strict rn, matching JAX.
// ---------------------------------------------------------------------------
__global__ void normalize_kernel(const float* __restrict__ env,
                                 float* __restrict__ out) {
    int t = blockIdx.x * blockDim.x + threadIdx.x;   // pixel-group id
    int base_pix = t * 4;
    if (base_pix >= HH * WW) return;

    // 12 contiguous floats of env / out, 16B-aligned (48B per group)
    const float4* e4 = reinterpret_cast<const float4*>(env + 12ll * t);
    float4 e0 = __ldg(e4 + 0);
    float4 e1 = __ldg(e4 + 1);
    float4 e2 = __ldg(e4 + 2);

    float ev[12] = { e0.x, e0.y, e0.z, e0.w,
                     e1.x, e1.y, e1.z, e1.w,
                     e2.x, e2.y, e2.z, e2.w };
    float ov[12];

    #pragma unroll
    for (int k = 0; k < 4; k++) {
        float4 acc = g_accum[base_pix + k];
        float denom = __fadd_rn(acc.w, BGW);
        ov[3 * k + 0] = __fdiv_rn(__fadd_rn(acc.x, __fmul_rn(BGW, ev[3 * k + 0])), denom);
        ov[3 * k + 1] = __fdiv_rn(__fadd_rn(acc.y, __fmul_rn(BGW, ev[3 * k + 1])), denom);
        ov[3 * k + 2] = __fdiv_rn(__fadd_rn(acc.z, __fmul_rn(BGW, ev[3 * k + 2])), denom);
    }

    float4* o4 = reinterpret_cast<float4*>(out + 12ll * t);
    o4[0] = make_float4(ov[0], ov[1], ov[2],  ov[3]);
    o4[1] = make_float4(ov[4], ov[5], ov[6],  ov[7]);
    o4[2] = make_float4(ov[8], ov[9], ov[10], ov[11]);
}

// ---------------------------------------------------------------------------
// Launch: memset accum -> splat -> normalize (all on default stream, capturable)
// Inputs (metadata order): 0=cam_type(int,1), 1=camera(16 f32),
//                          2=points(N*6 f32), 3=environment(H*W*3 f32)
// ---------------------------------------------------------------------------
extern "C" void kernel_launch(void* const* d_in, const int* in_sizes, int n_in,
                              void* d_out, int out_size) {
    const float* camera = (const float*)d_in[1];
    const float* points = (const float*)d_in[2];
    const float* env    = (const float*)d_in[3];
    float* out          = (float*)d_out;

    int n = in_sizes[2] / 6;

    void* accum_addr = nullptr;
    cudaGetSymbolAddress(&accum_addr, g_accum);
    cudaMemsetAsync(accum_addr, 0, sizeof(float4) * HH * WW, 0);

    {
        int threads = 256;
        int blocks = (n + threads - 1) / threads;
        splat_kernel<<<blocks, threads>>>(points, camera, n);
    }
    {
        int groups = (HH * WW) / 4;
        int threads = 256;
        int blocks = (groups + threads - 1) / threads;
        normalize_kernel<<<blocks, threads>>>(env, out);
    }
}